// round 17
// baseline (speedup 1.0000x reference)
#include <cuda_runtime.h>
#include <cuda_fp16.h>

#define NCTA 128
#define NTHR 512
#define Tn   512
#define TPn  544

// SMEM byte map
#define SM_B      0                   // 48KB weight fragments (fp16 hi only), uint2
#define SM_Z1     49152               // zbuf kp0 partials: 32*257*4 = 32896 B
#define SM_Z2     (SM_Z1 + 32896)     // zbuf kp1 partials
#define SM_MISC   (SM_Z2 + 32896)
#define SM_TOTAL  (SM_MISC + 256)

// uint2 index for B fragment block (m matrix, q k-chunk, nt n-tile, L lane)
#define BOFF2(m,q,nt,L) (((((m)*32+(q))*2+(nt))*32+(L)))

__device__ __align__(16) unsigned g_h1[2][131072];  // fp16 hi plane, A-frag order
__device__ __align__(16) unsigned g_h2[2][131072];
__device__ float    g_opart[256 * NCTA];            // [b][cta]
__device__ float    g_out[TPn * 256];               // [t][b], raw (no bl)
__device__ unsigned g_flags[NCTA];

__device__ __forceinline__ float sigf(float x) { return 1.f / (1.f + __expf(-x)); }
__device__ __forceinline__ float tanhf_fast(float x) {
  float e = __expf(2.f * x);                  // +inf / 0 at tails -> +-1 exactly
  return 1.f - __fdividef(2.f, e + 1.f);
}

__device__ __forceinline__ void mma16816(float* c, const uint4& a,
                                         unsigned b0, unsigned b1) {
  asm volatile(
      "mma.sync.aligned.m16n8k16.row.col.f32.f16.f16.f32 "
      "{%0,%1,%2,%3},{%4,%5,%6,%7},{%8,%9},{%0,%1,%2,%3};\n"
      : "+f"(c[0]), "+f"(c[1]), "+f"(c[2]), "+f"(c[3])
      : "r"(a.x), "r"(a.y), "r"(a.z), "r"(a.w), "r"(b0), "r"(b1));
}

__device__ __forceinline__ uint4 ldcg128(const uint4* p) {
  uint4 v;
  asm volatile("ld.global.cg.v4.u32 {%0,%1,%2,%3}, [%4];"
               : "=r"(v.x), "=r"(v.y), "=r"(v.z), "=r"(v.w) : "l"(p));
  return v;
}
__device__ __forceinline__ void stcg32(unsigned* p, unsigned v) {
  asm volatile("st.global.cg.u32 [%0], %1;" :: "l"(p), "r"(v) : "memory");
}
__device__ __forceinline__ void stcg32f(float* p, float v) {
  asm volatile("st.global.cg.f32 [%0], %1;" :: "l"(p), "f"(v) : "memory");
}

__device__ __forceinline__ void grid_barrier(unsigned& gen) {
  __threadfence();
  __syncthreads();
  ++gen;
  if (threadIdx.x == 0)
    asm volatile("st.release.gpu.u32 [%0], %1;" :: "l"(&g_flags[blockIdx.x]), "r"(gen));
  if (threadIdx.x < NCTA) {
    unsigned v;
    do {
      asm volatile("ld.acquire.gpu.u32 %0, [%1];" : "=r"(v) : "l"(&g_flags[threadIdx.x]));
    } while ((int)(v - gen) < 0);
  }
  __syncthreads();
}

// write h[b][u0..u0+3] as fp16 hi plane in A-fragment order
__device__ __forceinline__ void h_write(unsigned* gb, int b, int cta, const float* hv) {
  int q = cta >> 2, kcb = (cta & 3) * 4, mtg = b >> 4;
  __half hh[4];
#pragma unroll
  for (int u = 0; u < 4; ++u) hh[u] = __float2half_rn(hv[u]);
#pragma unroll
  for (int j = 0; j < 2; ++j) {
    int kc0 = kcb + 2 * j;
    int L   = ((b & 7) << 2) | ((kc0 & 7) >> 1);
    int rg  = ((b >> 3) & 1) | ((kc0 >> 3) << 1);
    __half2 vh = __halves2half2(hh[2 * j], hh[2 * j + 1]);
    stcg32(&gb[((q * 2 + 0) * 16 + mtg) * 128 + L * 4 + rg],
           *reinterpret_cast<unsigned*>(&vh));
  }
}

__global__ void __launch_bounds__(NTHR, 1) sine_rnn_kernel(
    const float* __restrict__ seq,
    const float* __restrict__ Wx1, const float* __restrict__ bx1,
    const float* __restrict__ Wh1, const float* __restrict__ bh1,
    const float* __restrict__ Wx2, const float* __restrict__ bx2,
    const float* __restrict__ Wh2, const float* __restrict__ bh2,
    const float* __restrict__ Wl,  const float* __restrict__ bl,
    float* __restrict__ out)
{
  extern __shared__ char smem[];
  const int tid  = threadIdx.x;
  const int lane = tid & 31;
  const int warp = tid >> 5;
  const int kp   = warp >> 3;   // K-part (q in [kp*16, kp*16+16))
  const int mpp  = warp & 7;    // M-part: batches [mpp*32, mpp*32+32)
  const int cta  = blockIdx.x;
  const int u0   = cta * 4;
  const float bl0 = __ldg(&bl[0]);

  float* misc = reinterpret_cast<float*>(smem + SM_MISC);
  // ---- init: weight fragments (fp16 hi only) + misc ----
  for (int idx = tid; idx < 3 * 512 * 16; idx += NTHR) {
    int m = idx >> 13, r = idx & 8191, k = r >> 4, gc = r & 15;
    int col = u0 + (gc & 3) + ((gc >> 2) << 9);
    const float* Wm = (m == 0) ? Wh2 : ((m == 1) ? Wx2 : Wh1);
    float v = Wm[k * 2048 + col];
    __half hi = __float2half_rn(v);
    int q = k >> 4, kc = k & 15, nt = gc >> 3, n = gc & 7;
    int L = (n << 2) | ((kc & 7) >> 1), rg = kc >> 3, hf = kc & 1;
    __half* hp = reinterpret_cast<__half*>(smem + SM_B);
    int base = BOFF2(m, q, nt, L) * 2;   // uint index of the uint2
    hp[(base + rg) * 2 + hf] = hi;
  }
  if (tid < 16) {
    int gc = tid;
    int col = u0 + (gc & 3) + ((gc >> 2) << 9);
    misc[gc]      = bx1[col] + bh1[col];
    misc[16 + gc] = bx2[col] + bh2[col];
    misc[32 + gc] = Wx1[col];
  }
  if (tid < 4) misc[48 + tid] = Wl[u0 + tid];
  __syncthreads();

  float c1s[4] = {0, 0, 0, 0}, c2s[4] = {0, 0, 0, 0};

  // h1(0) from x(0); zero slice of g_h2[1]
  if (tid < 256) {
    int b = tid;
    float x0 = __ldg(&seq[b * Tn]);
    float hv[4];
#pragma unroll
    for (int u = 0; u < 4; ++u) {
      float zi = fmaf(x0, misc[32 + u],      misc[u]);
      float zo = fmaf(x0, misc[32 + 8 + u],  misc[8 + u]);
      float zg = fmaf(x0, misc[32 + 12 + u], misc[12 + u]);
      float c = sigf(zi) * tanhf_fast(zg);
      c1s[u] = c;
      hv[u] = sigf(zo) * tanhf_fast(c);
    }
    h_write(g_h1[0], b, cta, hv);
  }
  for (int i = tid; i < 1024; i += NTHR) g_h2[1][cta * 1024 + i] = 0u;

  unsigned gen;
  asm volatile("ld.acquire.gpu.u32 %0, [%1];" : "=r"(gen) : "l"(&g_flags[cta]));
  grid_barrier(gen);

  const uint2* Bsm = reinterpret_cast<const uint2*>(smem + SM_B);

  for (int t = 0; t < TPn; ++t) {
    const bool pred = (t >= Tn - 1);

    const uint4* pH2 = reinterpret_cast<const uint4*>(g_h2[(t ^ 1) & 1]);
    const uint4* pH1 = reinterpret_cast<const uint4*>(g_h1[t & 1]);

    float z2a[2][2][4], z1a[2][2][4];   // [mt][nt][ci]
#pragma unroll
    for (int i = 0; i < 16; ++i) {
      reinterpret_cast<float*>(z2a)[i] = 0.f;
      reinterpret_cast<float*>(z1a)[i] = 0.f;
    }

    // per-warp rotated q order: decorrelate warps' L2 bursts
    auto qrot = [&](int p) { return kp * 16 + ((p + 2 * mpp) & 15); };

    // chunk cc = p*2 + ph ; ph: 0 = h2 hi (Wh2), 1 = h1 hi (Wx2+Wh1)
    auto loadA = [&](int cc, uint4* a) {
      int q = qrot(cc >> 1), ph = cc & 1;
      const uint4* g = (ph ? pH1 : pH2) + ((q * 2) * 16 + mpp * 2) * 32 + lane;
      a[0] = ldcg128(g);
      a[1] = ldcg128(g + 32);
    };

    uint2 BqA[6], BqB[6];
    auto loadBqTo = [&](uint2 (&Bq)[6], int q) {
#pragma unroll
      for (int m = 0; m < 3; ++m)
#pragma unroll
        for (int nt = 0; nt < 2; ++nt)
          Bq[m * 2 + nt] = Bsm[BOFF2(m, q, nt, lane)];
    };

    uint4 ar[6][2];
#pragma unroll
    for (int i = 0; i < 6; ++i) loadA(i, ar[i]);
    loadBqTo(BqA, qrot(0));

    // overlap o(t-1) reduce with in-flight LDGs
    if (t >= 1 && t <= Tn - 1 && warp < 2) {
      int ob = 2 * cta + warp;
      float4 v = __ldcg(reinterpret_cast<const float4*>(g_opart + ob * NCTA) + lane);
      float p = v.x + v.y + v.z + v.w;
#pragma unroll
      for (int off = 16; off; off >>= 1) p += __shfl_xor_sync(0xffffffffu, p, off);
      if (lane == 0) stcg32f(&g_out[(t - 1) * 256 + ob], p);
    }

    // one q-pair: ph0 then ph1, B double-buffered, ring refill
    auto stepPair = [&](int p, uint2 (&Bc)[6], uint2 (&Bn)[6]) {
      if (p < 15) loadBqTo(Bn, qrot(p + 1));
      int cc0 = 2 * p, cc1 = 2 * p + 1;
#pragma unroll
      for (int mt = 0; mt < 2; ++mt)
#pragma unroll
        for (int nt = 0; nt < 2; ++nt)
          mma16816(z2a[mt][nt], ar[cc0 % 6][mt], Bc[nt].x, Bc[nt].y);
      if (cc0 < 26) loadA(cc0 + 6, ar[cc0 % 6]);
#pragma unroll
      for (int mt = 0; mt < 2; ++mt)
#pragma unroll
        for (int nt = 0; nt < 2; ++nt) {
          mma16816(z2a[mt][nt], ar[cc1 % 6][mt], Bc[2 + nt].x, Bc[2 + nt].y);
          mma16816(z1a[mt][nt], ar[cc1 % 6][mt], Bc[4 + nt].x, Bc[4 + nt].y);
        }
      if (cc1 < 26) loadA(cc1 + 6, ar[cc1 % 6]);
    };

#pragma unroll
    for (int p = 0; p < 16; p += 2) {
      stepPair(p,     BqA, BqB);
      stepPair(p + 1, BqB, BqA);
    }

    // ---- dual-zbuf K-reduce: kp0 -> zb1, kp1 -> zb2, epilogue adds ----
    {
      float* zbm = reinterpret_cast<float*>(smem + (kp ? SM_Z2 : SM_Z1));
#pragma unroll
      for (int mt = 0; mt < 2; ++mt)
#pragma unroll
        for (int nt = 0; nt < 2; ++nt)
#pragma unroll
          for (int ci = 0; ci < 4; ++ci) {
            int b  = mpp * 32 + mt * 16 + (lane >> 2) + 8 * (ci >> 1);
            int gc = nt * 8 + (lane & 3) * 2 + (ci & 1);
            zbm[gc * 257 + b]        = z2a[mt][nt][ci];
            zbm[(16 + gc) * 257 + b] = z1a[mt][nt][ci];
          }
    }
    __syncthreads();

    // ---- epilogue layer 2 -> h2(t), opart ----
    const float* zb1 = reinterpret_cast<const float*>(smem + SM_Z1);
    const float* zb2 = reinterpret_cast<const float*>(smem + SM_Z2);
    if (tid < 256) {
      int b = tid;
      float hv[4], op = 0.f;
#pragma unroll
      for (int u = 0; u < 4; ++u) {
        float zi = zb1[(u) * 257 + b]      + zb2[(u) * 257 + b]      + misc[16 + u];
        float zf = zb1[(4 + u) * 257 + b]  + zb2[(4 + u) * 257 + b]  + misc[16 + 4 + u];
        float zo = zb1[(8 + u) * 257 + b]  + zb2[(8 + u) * 257 + b]  + misc[16 + 8 + u];
        float zg = zb1[(12 + u) * 257 + b] + zb2[(12 + u) * 257 + b] + misc[16 + 12 + u];
        float c = sigf(zf) * c2s[u] + sigf(zi) * tanhf_fast(zg);
        c2s[u] = c;
        hv[u] = sigf(zo) * tanhf_fast(c);
        op = fmaf(hv[u], misc[48 + u], op);
      }
      h_write(g_h2[t & 1], b, cta, hv);
      stcg32f(&g_opart[b * NCTA + cta], op);
    }

    // ---- next input ----
    float xnext = 0.f;
    if (!pred) {
      if (tid < 256) xnext = __ldg(&seq[tid * Tn + (t + 1)]);
    } else {
      grid_barrier(gen);
      if (warp < 2) {
        int ob = 2 * cta + warp;
        float4 v = __ldcg(reinterpret_cast<const float4*>(g_opart + ob * NCTA) + lane);
        float p = v.x + v.y + v.z + v.w;
#pragma unroll
        for (int off = 16; off; off >>= 1) p += __shfl_xor_sync(0xffffffffu, p, off);
        if (lane == 0) stcg32f(&g_out[t * 256 + ob], p);
      }
      grid_barrier(gen);
      if (tid < 256) xnext = __ldcg(&g_out[t * 256 + tid]) + bl0;
    }

    // ---- epilogue layer 1 -> h1(t+1) ----
    if (tid < 256) {
      int b = tid;
      float hv[4];
#pragma unroll
      for (int u = 0; u < 4; ++u) {
        float z1s0 = zb1[(16 + u) * 257 + b]      + zb2[(16 + u) * 257 + b];
        float z1s1 = zb1[(16 + 4 + u) * 257 + b]  + zb2[(16 + 4 + u) * 257 + b];
        float z1s2 = zb1[(16 + 8 + u) * 257 + b]  + zb2[(16 + 8 + u) * 257 + b];
        float z1s3 = zb1[(16 + 12 + u) * 257 + b] + zb2[(16 + 12 + u) * 257 + b];
        float zi = fmaf(xnext, misc[32 + u],      z1s0 + misc[u]);
        float zf = fmaf(xnext, misc[32 + 4 + u],  z1s1 + misc[4 + u]);
        float zo = fmaf(xnext, misc[32 + 8 + u],  z1s2 + misc[8 + u]);
        float zg = fmaf(xnext, misc[32 + 12 + u], z1s3 + misc[12 + u]);
        float c = sigf(zf) * c1s[u] + sigf(zi) * tanhf_fast(zg);
        c1s[u] = c;
        hv[u] = sigf(zo) * tanhf_fast(c);
      }
      h_write(g_h1[(t + 1) & 1], b, cta, hv);
    }
    grid_barrier(gen);
  }

  // out[b][tp] = o + bl
  for (int idx = cta * NTHR + tid; idx < TPn * 256; idx += NCTA * NTHR) {
    int b = idx / TPn, tp = idx - b * TPn;
    out[idx] = __ldcg(&g_out[tp * 256 + b]) + bl0;
  }
}

extern "C" void kernel_launch(void* const* d_in, const int* in_sizes, int n_in,
                              void* d_out, int out_size) {
  (void)in_sizes; (void)n_in; (void)out_size;
  const float* seq = (const float*)d_in[0];
  const float* Wx1 = (const float*)d_in[2];
  const float* bx1 = (const float*)d_in[3];
  const float* Wh1 = (const float*)d_in[4];
  const float* bh1 = (const float*)d_in[5];
  const float* Wx2 = (const float*)d_in[6];
  const float* bx2 = (const float*)d_in[7];
  const float* Wh2 = (const float*)d_in[8];
  const float* bh2 = (const float*)d_in[9];
  const float* Wl  = (const float*)d_in[10];
  const float* bl  = (const float*)d_in[11];

  cudaFuncSetAttribute(sine_rnn_kernel,
                       cudaFuncAttributeMaxDynamicSharedMemorySize, SM_TOTAL);
  sine_rnn_kernel<<<NCTA, NTHR, SM_TOTAL>>>(
      seq, Wx1, bx1, Wh1, bh1, Wx2, bx2, Wh2, bh2, Wl, bl, (float*)d_out);
}